// round 1
// baseline (speedup 1.0000x reference)
#include <cuda_runtime.h>
#include <cuda_bf16.h>

// Problem constants
#define BB 4
#define CC 64
#define HH 192
#define WW 192
#define CS (HH*WW)            // channel stride = 36864
#define NT (BB*CC*HH*WW)      // 9437184 elems per [B,C,H,W] tensor
#define SP 193                // padded row stride for score matrix in SMEM

// ---------------- static scratch (no runtime allocation allowed) ----------------
__device__ float g_t[NT];
__device__ float g_a[NT];
__device__ float g_Q1[NT];
__device__ float g_K1[NT];
__device__ float g_Q2[NT];
__device__ float g_K2[NT];
__device__ float g_r2l1[NT];
__device__ float g_l2r1[NT];

// =================================================================================
// Conv 3x3, stride 1, pad 1, C=64 -> C=64.
// mode 0: y = conv(x)+b ; mode 1: y = relu(conv(x)+b) ; mode 2: y = skip + conv(x)+b
// CTA: 256 threads, 16x16 pixel tile, all 64 output channels in registers.
// Input channels processed in chunks of 8 staged in SMEM together with the
// corresponding weight slice (layout [c][k][o], float4 over o for broadcast LDS.128).
// =================================================================================
__global__ void __launch_bounds__(256) conv3x3_kernel(
    const float* __restrict__ x, const float* __restrict__ w,
    const float* __restrict__ bias, const float* __restrict__ skip,
    float* __restrict__ y, int mode)
{
    __shared__ __align__(16) float in_s[8 * 18 * 20];   // [c][iy][ix], ix padded to 20
    __shared__ __align__(16) float ws[8 * 9 * 64];      // [c][k][o]

    const int b  = blockIdx.z;
    const int ty = blockIdx.y, tx = blockIdx.x;
    const int tid = threadIdx.x;
    const int py = tid >> 4, px = tid & 15;
    const int gy = ty * 16 + py, gx = tx * 16 + px;

    float acc[64];
#pragma unroll
    for (int o = 0; o < 64; o++) acc[o] = __ldg(&bias[o]);

    for (int c0 = 0; c0 < 64; c0 += 8) {
        __syncthreads();  // protect previous iteration's SMEM reads
        // stage input tile (18x18 halo, zero padded at image border)
        for (int i = tid; i < 8 * 18 * 18; i += 256) {
            int c = i / 324, r = i % 324;
            int iy = r / 18, ix = r % 18;
            int ggy = ty * 16 + iy - 1, ggx = tx * 16 + ix - 1;
            float v = 0.f;
            if (ggy >= 0 && ggy < HH && ggx >= 0 && ggx < WW)
                v = x[((b * 64 + c0 + c) * HH + ggy) * WW + ggx];
            in_s[c * 360 + iy * 20 + ix] = v;
        }
        // stage weights: ws[(c*9+k)*64 + o] = w[o*576 + (c0+c)*9 + k]
        for (int i = tid; i < 8 * 9 * 64; i += 256) {
            int o = i & 63, ck = i >> 6;
            int c = ck / 9, k = ck % 9;
            ws[i] = __ldg(&w[o * 576 + (c0 + c) * 9 + k]);
        }
        __syncthreads();

#pragma unroll
        for (int c = 0; c < 8; c++) {
            float xv[9];
#pragma unroll
            for (int ky = 0; ky < 3; ky++)
#pragma unroll
                for (int kx = 0; kx < 3; kx++)
                    xv[ky * 3 + kx] = in_s[c * 360 + (py + ky) * 20 + (px + kx)];
            const float4* w4 = (const float4*)&ws[c * 9 * 64];
#pragma unroll
            for (int k = 0; k < 9; k++) {
#pragma unroll
                for (int o4 = 0; o4 < 16; o4++) {
                    float4 wv = w4[k * 16 + o4];
                    acc[o4 * 4 + 0] = fmaf(xv[k], wv.x, acc[o4 * 4 + 0]);
                    acc[o4 * 4 + 1] = fmaf(xv[k], wv.y, acc[o4 * 4 + 1]);
                    acc[o4 * 4 + 2] = fmaf(xv[k], wv.z, acc[o4 * 4 + 2]);
                    acc[o4 * 4 + 3] = fmaf(xv[k], wv.w, acc[o4 * 4 + 3]);
                }
            }
        }
    }

    const int obase = ((b * 64) * HH + gy) * WW + gx;
#pragma unroll
    for (int o = 0; o < 64; o++) {
        float v = acc[o];
        int off = obase + o * CS;
        if (mode == 1)      v = fmaxf(v, 0.f);
        else if (mode == 2) v += skip[off];
        y[off] = v;
    }
}

// =================================================================================
// Fused attention: one CTA per (b, h). 256 threads = 8 warps.
// SMEM: Sb[192][193] score matrix (148 KB) + fb[64][192] feature buffer (48 KB).
// Score tensors never hit global memory.
// =================================================================================

__device__ __forceinline__ void load_feat(float* fb, const float* __restrict__ g,
                                          int rb, int tid)
{
#pragma unroll
    for (int k = 0; k < 12; k++) {
        int i4 = tid + k * 256;          // 0..3071, covers 64*192/4
        int c = i4 / 48, v4 = i4 % 48;
        float4 val = *(const float4*)(g + rb + c * CS + v4 * 4);
        ((float4*)fb)[i4] = val;
    }
}

// S[w][v] = sum_c Q[c][w] * K[c][v]; K staged in fb, Q via broadcast LDG.128
__device__ __forceinline__ void compute_S(const float* __restrict__ Q, int rb,
                                          const float* fb, float* Sb,
                                          int wid, int lane)
{
    const int w0 = wid * 24;
    for (int g = 0; g < 6; g++) {
        const int wr = w0 + g * 4;
        float acc[4][6];
#pragma unroll
        for (int r = 0; r < 4; r++)
#pragma unroll
            for (int j = 0; j < 6; j++) acc[r][j] = 0.f;

        for (int c = 0; c < 64; c += 4) {
            float4 qa[4];
#pragma unroll
            for (int cc = 0; cc < 4; cc++)
                qa[cc] = __ldg((const float4*)(Q + rb + (c + cc) * CS + wr));
#pragma unroll
            for (int cc = 0; cc < 4; cc++) {
#pragma unroll
                for (int j = 0; j < 6; j++) {
                    float kv = fb[(c + cc) * 192 + lane + 32 * j];
                    acc[0][j] = fmaf(qa[cc].x, kv, acc[0][j]);
                    acc[1][j] = fmaf(qa[cc].y, kv, acc[1][j]);
                    acc[2][j] = fmaf(qa[cc].z, kv, acc[2][j]);
                    acc[3][j] = fmaf(qa[cc].w, kv, acc[3][j]);
                }
            }
        }
#pragma unroll
        for (int r = 0; r < 4; r++)
#pragma unroll
            for (int j = 0; j < 6; j++)
                Sb[(wr + r) * SP + lane + 32 * j] = acc[r][j];
    }
}

__device__ __forceinline__ void softmax_rows(float* Sb, int wid, int lane)
{
    for (int r = wid * 24; r < wid * 24 + 24; r++) {
        float v[6];
        float m = -1e30f;
#pragma unroll
        for (int j = 0; j < 6; j++) {
            v[j] = Sb[r * SP + lane + 32 * j];
            m = fmaxf(m, v[j]);
        }
#pragma unroll
        for (int o = 16; o > 0; o >>= 1)
            m = fmaxf(m, __shfl_xor_sync(0xffffffffu, m, o));
        float s = 0.f;
#pragma unroll
        for (int j = 0; j < 6; j++) { v[j] = __expf(v[j] - m); s += v[j]; }
#pragma unroll
        for (int o = 16; o > 0; o >>= 1)
            s += __shfl_xor_sync(0xffffffffu, s, o);
        float inv = 1.0f / s;
#pragma unroll
        for (int j = 0; j < 6; j++)
            Sb[r * SP + lane + 32 * j] = v[j] * inv;
    }
}

// TRANSP=false : out[c][w] = sum_v f[c][v] * S[w][v]   (apply_score)
// TRANSP=true  : out[c][w] = sum_v f[c][v] * S[v][w]   (apply_score_T)
template <bool TRANSP>
__device__ __forceinline__ void apply_gemm(const float* fb, const float* Sb,
                                           float t[48], int wid, int lane)
{
    const int c0 = wid * 8;
#pragma unroll
    for (int i = 0; i < 48; i++) t[i] = 0.f;
    for (int v = 0; v < 192; v += 4) {
        float f[8][4];
#pragma unroll
        for (int ci = 0; ci < 8; ci++) {
            float4 x4 = *(const float4*)&fb[(c0 + ci) * 192 + v];
            f[ci][0] = x4.x; f[ci][1] = x4.y; f[ci][2] = x4.z; f[ci][3] = x4.w;
        }
#pragma unroll
        for (int dv = 0; dv < 4; dv++) {
#pragma unroll
            for (int j = 0; j < 6; j++) {
                float s = TRANSP ? Sb[(v + dv) * SP + lane + 32 * j]
                                 : Sb[(lane + 32 * j) * SP + (v + dv)];
#pragma unroll
                for (int ci = 0; ci < 8; ci++)
                    t[ci * 6 + j] = fmaf(f[ci][dv], s, t[ci * 6 + j]);
            }
        }
    }
}

__device__ __forceinline__ void emit_init(float* dst, float* scratch,
                                          const float* base, const float t[48],
                                          int rb, int wid, int lane)
{
    const int c0 = wid * 8;
#pragma unroll
    for (int ci = 0; ci < 8; ci++)
#pragma unroll
        for (int j = 0; j < 6; j++) {
            int off = rb + (c0 + ci) * CS + lane + 32 * j;
            float v = t[ci * 6 + j];
            scratch[off] = v;
            dst[off] = base[off] + v;
        }
}

__device__ __forceinline__ void emit_add(float* dst, const float t[48],
                                         int rb, int wid, int lane)
{
    const int c0 = wid * 8;
#pragma unroll
    for (int ci = 0; ci < 8; ci++)
#pragma unroll
        for (int j = 0; j < 6; j++) {
            int off = rb + (c0 + ci) * CS + lane + 32 * j;
            dst[off] += t[ci * 6 + j];
        }
}

__global__ void __launch_bounds__(256, 1) attn_kernel(
    const float* __restrict__ low1, const float* __restrict__ low2,
    const float* __restrict__ Q1, const float* __restrict__ K1,
    const float* __restrict__ Q2, const float* __restrict__ K2,
    float* __restrict__ r2l1s, float* __restrict__ l2r1s,
    float* __restrict__ outL, float* __restrict__ outR)
{
    extern __shared__ float sm[];
    float* Sb = sm;                 // 192 * 193
    float* fb = sm + 192 * SP;      // 64 * 192

    const int h = blockIdx.x, b = blockIdx.y;
    const int tid = threadIdx.x, wid = tid >> 5, lane = tid & 31;
    const int rb = b * 64 * CS + h * WW;
    float t[48];

    // ---- stage 1: S1 = softmax(Q1^T K1) ----
    load_feat(fb, K1, rb, tid); __syncthreads();
    compute_S(Q1, rb, fb, Sb, wid, lane); __syncthreads();
    softmax_rows(Sb, wid, lane); __syncthreads();

    // r2l1 = low2 @ S1^T  -> left, scratch
    load_feat(fb, low2, rb, tid); __syncthreads();
    apply_gemm<false>(fb, Sb, t, wid, lane);
    emit_init(outL, r2l1s, low1, t, rb, wid, lane);
    __syncthreads();

    // l2r1 = low1 @ S1    -> right, scratch
    load_feat(fb, low1, rb, tid); __syncthreads();
    apply_gemm<true>(fb, Sb, t, wid, lane);
    emit_init(outR, l2r1s, low2, t, rb, wid, lane);
    __syncthreads();

    // ---- stage 2: S2 = softmax(Q2^T K2) ----
    load_feat(fb, K2, rb, tid); __syncthreads();
    compute_S(Q2, rb, fb, Sb, wid, lane); __syncthreads();
    softmax_rows(Sb, wid, lane); __syncthreads();

    // r2l2 -> left
    load_feat(fb, low2, rb, tid); __syncthreads();
    apply_gemm<false>(fb, Sb, t, wid, lane);
    emit_add(outL, t, rb, wid, lane); __syncthreads();

    // l2r2 -> right
    load_feat(fb, low1, rb, tid); __syncthreads();
    apply_gemm<true>(fb, Sb, t, wid, lane);
    emit_add(outR, t, rb, wid, lane); __syncthreads();

    // l2r2l = l2r1 @ S2^T -> left
    load_feat(fb, l2r1s, rb, tid); __syncthreads();
    apply_gemm<false>(fb, Sb, t, wid, lane);
    emit_add(outL, t, rb, wid, lane); __syncthreads();

    // r2l2r = r2l1 @ S2   -> right
    load_feat(fb, r2l1s, rb, tid); __syncthreads();
    apply_gemm<true>(fb, Sb, t, wid, lane);
    emit_add(outR, t, rb, wid, lane);
}

// =================================================================================
extern "C" void kernel_launch(void* const* d_in, const int* in_sizes, int n_in,
                              void* d_out, int out_size)
{
    const float* low1   = (const float*)d_in[0];
    const float* low2   = (const float*)d_in[1];
    const float* fe1_w1 = (const float*)d_in[2];
    const float* fe1_b1 = (const float*)d_in[3];
    const float* fe1_w2 = (const float*)d_in[4];
    const float* fe1_b2 = (const float*)d_in[5];
    const float* fe2_w1 = (const float*)d_in[6];
    const float* fe2_b1 = (const float*)d_in[7];
    const float* fe2_w2 = (const float*)d_in[8];
    const float* fe2_b2 = (const float*)d_in[9];
    const float* conv_w = (const float*)d_in[10];
    const float* conv_b = (const float*)d_in[11];
    float* out = (float*)d_out;

    float *t_, *a_, *q1, *k1, *q2, *k2, *r2l1, *l2r1;
    cudaGetSymbolAddress((void**)&t_,   g_t);
    cudaGetSymbolAddress((void**)&a_,   g_a);
    cudaGetSymbolAddress((void**)&q1,   g_Q1);
    cudaGetSymbolAddress((void**)&k1,   g_K1);
    cudaGetSymbolAddress((void**)&q2,   g_Q2);
    cudaGetSymbolAddress((void**)&k2,   g_K2);
    cudaGetSymbolAddress((void**)&r2l1, g_r2l1);
    cudaGetSymbolAddress((void**)&l2r1, g_l2r1);

    const dim3 cgrid(WW / 16, HH / 16, BB);

    struct Combo { const float* src; const float *w1, *b1, *w2, *b2; float* dst; };
    Combo combos[4] = {
        { low1, fe1_w1, fe1_b1, fe1_w2, fe1_b2, q1 },
        { low2, fe1_w1, fe1_b1, fe1_w2, fe1_b2, k1 },
        { low1, fe2_w1, fe2_b1, fe2_w2, fe2_b2, q2 },
        { low2, fe2_w1, fe2_b1, fe2_w2, fe2_b2, k2 },
    };
    for (int i = 0; i < 4; i++) {
        // t = relu(conv(src, w1) + b1)
        conv3x3_kernel<<<cgrid, 256>>>(combos[i].src, combos[i].w1, combos[i].b1,
                                       nullptr, t_, 1);
        // a = src + conv(t, w2) + b2
        conv3x3_kernel<<<cgrid, 256>>>(t_, combos[i].w2, combos[i].b2,
                                       combos[i].src, a_, 2);
        // dst = conv(a, conv_w) + conv_b
        conv3x3_kernel<<<cgrid, 256>>>(a_, conv_w, conv_b, nullptr,
                                       combos[i].dst, 0);
    }

    const int smem_bytes = (192 * SP + 64 * 192) * (int)sizeof(float); // 197376
    cudaFuncSetAttribute(attn_kernel,
                         cudaFuncAttributeMaxDynamicSharedMemorySize, smem_bytes);
    attn_kernel<<<dim3(HH, BB), 256, smem_bytes>>>(
        low1, low2, q1, k1, q2, k2, r2l1, l2r1, out, out + NT);
}

// round 2
// speedup vs baseline: 1.7057x; 1.7057x over previous
#include <cuda_runtime.h>
#include <cuda_bf16.h>

typedef unsigned int u32;

// Problem constants
#define BB 4
#define CC 64
#define HH 192
#define WW 192
#define CS (HH*WW)            // channel stride = 36864
#define NT (BB*CC*HH*WW)      // elems per [B,C,H,W] tensor
#define SP 193                // padded row stride for score matrix in SMEM

// ---------------- static scratch (no runtime allocation allowed) ----------------
__device__ float g_t[NT];
__device__ float g_a[NT];
__device__ float g_Q1[NT];
__device__ float g_K1[NT];
__device__ float g_Q2[NT];
__device__ float g_K2[NT];
__device__ float g_r2l1[NT];
__device__ float g_l2r1[NT];

// =================================================================================
// Tensor-core conv 3x3 (stride 1, pad 1, C64->C64) via mma.sync bf16x3 split.
// Implicit GEMM: D[pixel, och] = sum_{tap, c} X[pixel, (tap,c)] * W[(tap,c), och]
// CTA: 256 thr (8 warps), pixel tile 16x16, N=64 och. Warp = 2 image rows x 64 och.
// bf16x3: x = hi + lo (both bf16), D += Ah*Bh + Ah*Bl + Al*Bh  (fp32 accumulate)
// mode 0: y = conv+b ; 1: relu(conv+b) ; 2: skip + conv + b
// =================================================================================

__device__ __forceinline__ void split_pack(float ev, float ov, u32 &hi, u32 &lo)
{
    __nv_bfloat16 eh = __float2bfloat16(ev);
    __nv_bfloat16 oh = __float2bfloat16(ov);
    __nv_bfloat16 el = __float2bfloat16(ev - __bfloat162float(eh));
    __nv_bfloat16 ol = __float2bfloat16(ov - __bfloat162float(oh));
    hi = (u32)__bfloat16_as_ushort(eh) | ((u32)__bfloat16_as_ushort(oh) << 16);
    lo = (u32)__bfloat16_as_ushort(el) | ((u32)__bfloat16_as_ushort(ol) << 16);
}

__device__ __forceinline__ void mma16816(float c[4],
                                         u32 a0, u32 a1, u32 a2, u32 a3,
                                         u32 b0, u32 b1)
{
    asm volatile(
        "mma.sync.aligned.m16n8k16.row.col.f32.bf16.bf16.f32 "
        "{%0,%1,%2,%3}, {%4,%5,%6,%7}, {%8,%9}, {%0,%1,%2,%3};"
        : "+f"(c[0]), "+f"(c[1]), "+f"(c[2]), "+f"(c[3])
        : "r"(a0), "r"(a1), "r"(a2), "r"(a3), "r"(b0), "r"(b1));
}

// SMEM layout (u32 units):
//  Hhi [32][18][20]  (c2, y, x)  -> 11520 u32   (channel-pair stride 360 == 8 mod 32)
//  Hlo [32][18][20]               -> 11520
//  Whi [32][72]      (c2, och)    ->  2304      (stride 72 == 8 mod 32)
//  Wlo [32][72]                   ->  2304
//  total 27648 u32 = 110592 bytes  -> 2 CTAs/SM
#define CONV_SMEM_BYTES 110592

__global__ void __launch_bounds__(256, 2) conv3x3_mma(
    const float* __restrict__ x, const float* __restrict__ w,
    const float* __restrict__ bias, const float* __restrict__ skip,
    float* __restrict__ y, int mode)
{
    extern __shared__ u32 sm[];
    u32* Hhi = sm;
    u32* Hlo = sm + 11520;
    u32* Whi = sm + 23040;
    u32* Wlo = sm + 25344;

    const int b = blockIdx.z, ty = blockIdx.y, tx = blockIdx.x;
    const int tid = threadIdx.x, wid = tid >> 5, lane = tid & 31;
    const int g = lane >> 2, t = lane & 3;

    // ---- stage input halo (18x18, zero-padded at image border), bf16x2 hi/lo ----
    const int y0 = ty * 16 - 1, x0 = tx * 16 - 1;
    for (int i = tid; i < 32 * 18 * 18; i += 256) {
        int c2 = i / 324, r = i % 324;
        int yy = r / 18, xx = r % 18;
        int gy = y0 + yy, gx = x0 + xx;
        float ev = 0.f, ov = 0.f;
        if (gy >= 0 && gy < HH && gx >= 0 && gx < WW) {
            const float* p = x + ((b * 64 + 2 * c2) * HH + gy) * WW + gx;
            ev = p[0];
            ov = p[CS];
        }
        u32 h, l;
        split_pack(ev, ov, h, l);
        Hhi[c2 * 360 + yy * 20 + xx] = h;
        Hlo[c2 * 360 + yy * 20 + xx] = l;
    }

    float acc[2][8][4];
#pragma unroll
    for (int mi = 0; mi < 2; mi++)
#pragma unroll
        for (int n8 = 0; n8 < 8; n8++)
#pragma unroll
            for (int q = 0; q < 4; q++) acc[mi][n8][q] = 0.f;

    const int row0 = 2 * wid;   // warp's 2 image rows within the tile

    for (int tap = 0; tap < 9; tap++) {
        const int dy = tap / 3, dx = tap % 3;
        __syncthreads();   // protect previous tap's weight reads (and halo on iter 0)
        // ---- stage this tap's weights: Whi/Wlo[c2][och], pair = channels 2c2,2c2+1 ----
        for (int i = tid; i < 2048; i += 256) {
            int c2 = i >> 6, o = i & 63;
            float ev = __ldg(&w[o * 576 + (2 * c2) * 9 + tap]);
            float ov = __ldg(&w[o * 576 + (2 * c2 + 1) * 9 + tap]);
            u32 h, l;
            split_pack(ev, ov, h, l);
            Whi[c2 * 72 + o] = h;
            Wlo[c2 * 72 + o] = l;
        }
        __syncthreads();

#pragma unroll
        for (int ch = 0; ch < 4; ch++) {     // 4 k16-chunks = 8 channel-pairs each
            const int c2b = ch * 8;
            u32 ah[2][4], al[2][4];
#pragma unroll
            for (int mi = 0; mi < 2; mi++) {
                const int base = (row0 + mi + dy) * 20 + dx;
                const int rA = (c2b + t) * 360 + base;
                const int rB = (c2b + t + 4) * 360 + base;
                ah[mi][0] = Hhi[rA + g];
                ah[mi][1] = Hhi[rA + g + 8];
                ah[mi][2] = Hhi[rB + g];
                ah[mi][3] = Hhi[rB + g + 8];
                al[mi][0] = Hlo[rA + g];
                al[mi][1] = Hlo[rA + g + 8];
                al[mi][2] = Hlo[rB + g];
                al[mi][3] = Hlo[rB + g + 8];
            }
#pragma unroll
            for (int n8 = 0; n8 < 8; n8++) {
                const int o = n8 * 8 + g;
                u32 bh0 = Whi[(c2b + t) * 72 + o];
                u32 bh1 = Whi[(c2b + t + 4) * 72 + o];
                u32 bl0 = Wlo[(c2b + t) * 72 + o];
                u32 bl1 = Wlo[(c2b + t + 4) * 72 + o];
#pragma unroll
                for (int mi = 0; mi < 2; mi++) {
                    mma16816(acc[mi][n8], ah[mi][0], ah[mi][1], ah[mi][2], ah[mi][3], bh0, bh1);
                    mma16816(acc[mi][n8], ah[mi][0], ah[mi][1], ah[mi][2], ah[mi][3], bl0, bl1);
                    mma16816(acc[mi][n8], al[mi][0], al[mi][1], al[mi][2], al[mi][3], bh0, bh1);
                }
            }
        }
    }

    // ---- epilogue: c0=C[g][2t], c1=C[g][2t+1], c2=C[g+8][2t], c3=C[g+8][2t+1] ----
    const int gyb = ty * 16 + row0, gxb = tx * 16;
#pragma unroll
    for (int n8 = 0; n8 < 8; n8++) {
#pragma unroll
        for (int mi = 0; mi < 2; mi++) {
            const int gy = gyb + mi;
#pragma unroll
            for (int q = 0; q < 4; q++) {
                const int och = n8 * 8 + 2 * t + (q & 1);
                const int px  = gxb + g + ((q >= 2) ? 8 : 0);
                float v = acc[mi][n8][q] + __ldg(&bias[och]);
                const int off = ((b * 64 + och) * HH + gy) * WW + px;
                if (mode == 1)      v = fmaxf(v, 0.f);
                else if (mode == 2) v += skip[off];
                y[off] = v;
            }
        }
    }
}

// =================================================================================
// Fused attention: one CTA per (b, h). 256 threads = 8 warps. (unchanged, passing)
// SMEM: Sb[192][193] score matrix + fb[64][192] feature buffer.
// =================================================================================

__device__ __forceinline__ void load_feat(float* fb, const float* __restrict__ g,
                                          int rb, int tid)
{
#pragma unroll
    for (int k = 0; k < 12; k++) {
        int i4 = tid + k * 256;
        int c = i4 / 48, v4 = i4 % 48;
        float4 val = *(const float4*)(g + rb + c * CS + v4 * 4);
        ((float4*)fb)[i4] = val;
    }
}

__device__ __forceinline__ void compute_S(const float* __restrict__ Q, int rb,
                                          const float* fb, float* Sb,
                                          int wid, int lane)
{
    const int w0 = wid * 24;
    for (int g = 0; g < 6; g++) {
        const int wr = w0 + g * 4;
        float acc[4][6];
#pragma unroll
        for (int r = 0; r < 4; r++)
#pragma unroll
            for (int j = 0; j < 6; j++) acc[r][j] = 0.f;

        for (int c = 0; c < 64; c += 4) {
            float4 qa[4];
#pragma unroll
            for (int cc = 0; cc < 4; cc++)
                qa[cc] = __ldg((const float4*)(Q + rb + (c + cc) * CS + wr));
#pragma unroll
            for (int cc = 0; cc < 4; cc++) {
#pragma unroll
                for (int j = 0; j < 6; j++) {
                    float kv = fb[(c + cc) * 192 + lane + 32 * j];
                    acc[0][j] = fmaf(qa[cc].x, kv, acc[0][j]);
                    acc[1][j] = fmaf(qa[cc].y, kv, acc[1][j]);
                    acc[2][j] = fmaf(qa[cc].z, kv, acc[2][j]);
                    acc[3][j] = fmaf(qa[cc].w, kv, acc[3][j]);
                }
            }
        }
#pragma unroll
        for (int r = 0; r < 4; r++)
#pragma unroll
            for (int j = 0; j < 6; j++)
                Sb[(wr + r) * SP + lane + 32 * j] = acc[r][j];
    }
}

__device__ __forceinline__ void softmax_rows(float* Sb, int wid, int lane)
{
    for (int r = wid * 24; r < wid * 24 + 24; r++) {
        float v[6];
        float m = -1e30f;
#pragma unroll
        for (int j = 0; j < 6; j++) {
            v[j] = Sb[r * SP + lane + 32 * j];
            m = fmaxf(m, v[j]);
        }
#pragma unroll
        for (int o = 16; o > 0; o >>= 1)
            m = fmaxf(m, __shfl_xor_sync(0xffffffffu, m, o));
        float s = 0.f;
#pragma unroll
        for (int j = 0; j < 6; j++) { v[j] = __expf(v[j] - m); s += v[j]; }
#pragma unroll
        for (int o = 16; o > 0; o >>= 1)
            s += __shfl_xor_sync(0xffffffffu, s, o);
        float inv = 1.0f / s;
#pragma unroll
        for (int j = 0; j < 6; j++)
            Sb[r * SP + lane + 32 * j] = v[j] * inv;
    }
}

template <bool TRANSP>
__device__ __forceinline__ void apply_gemm(const float* fb, const float* Sb,
                                           float t[48], int wid, int lane)
{
    const int c0 = wid * 8;
#pragma unroll
    for (int i = 0; i < 48; i++) t[i] = 0.f;
    for (int v = 0; v < 192; v += 4) {
        float f[8][4];
#pragma unroll
        for (int ci = 0; ci < 8; ci++) {
            float4 x4 = *(const float4*)&fb[(c0 + ci) * 192 + v];
            f[ci][0] = x4.x; f[ci][1] = x4.y; f[ci][2] = x4.z; f[ci][3] = x4.w;
        }
#pragma unroll
        for (int dv = 0; dv < 4; dv++) {
#pragma unroll
            for (int j = 0; j < 6; j++) {
                float s = TRANSP ? Sb[(v + dv) * SP + lane + 32 * j]
                                 : Sb[(lane + 32 * j) * SP + (v + dv)];
#pragma unroll
                for (int ci = 0; ci < 8; ci++)
                    t[ci * 6 + j] = fmaf(f[ci][dv], s, t[ci * 6 + j]);
            }
        }
    }
}

__device__ __forceinline__ void emit_init(float* dst, float* scratch,
                                          const float* base, const float t[48],
                                          int rb, int wid, int lane)
{
    const int c0 = wid * 8;
#pragma unroll
    for (int ci = 0; ci < 8; ci++)
#pragma unroll
        for (int j = 0; j < 6; j++) {
            int off = rb + (c0 + ci) * CS + lane + 32 * j;
            float v = t[ci * 6 + j];
            scratch[off] = v;
            dst[off] = base[off] + v;
        }
}

__device__ __forceinline__ void emit_add(float* dst, const float t[48],
                                         int rb, int wid, int lane)
{
    const int c0 = wid * 8;
#pragma unroll
    for (int ci = 0; ci < 8; ci++)
#pragma unroll
        for (int j = 0; j < 6; j++) {
            int off = rb + (c0 + ci) * CS + lane + 32 * j;
            dst[off] += t[ci * 6 + j];
        }
}

__global__ void __launch_bounds__(256, 1) attn_kernel(
    const float* __restrict__ low1, const float* __restrict__ low2,
    const float* __restrict__ Q1, const float* __restrict__ K1,
    const float* __restrict__ Q2, const float* __restrict__ K2,
    float* __restrict__ r2l1s, float* __restrict__ l2r1s,
    float* __restrict__ outL, float* __restrict__ outR)
{
    extern __shared__ float smf[];
    float* Sb = smf;
    float* fb = smf + 192 * SP;

    const int h = blockIdx.x, b = blockIdx.y;
    const int tid = threadIdx.x, wid = tid >> 5, lane = tid & 31;
    const int rb = b * 64 * CS + h * WW;
    float t[48];

    load_feat(fb, K1, rb, tid); __syncthreads();
    compute_S(Q1, rb, fb, Sb, wid, lane); __syncthreads();
    softmax_rows(Sb, wid, lane); __syncthreads();

    load_feat(fb, low2, rb, tid); __syncthreads();
    apply_gemm<false>(fb, Sb, t, wid, lane);
    emit_init(outL, r2l1s, low1, t, rb, wid, lane);
    __syncthreads();

    load_feat(fb, low1, rb, tid); __syncthreads();
    apply_gemm<true>(fb, Sb, t, wid, lane);
    emit_init(outR, l2r1s, low2, t, rb, wid, lane);
    __syncthreads();

    load_feat(fb, K2, rb, tid); __syncthreads();
    compute_S(Q2, rb, fb, Sb, wid, lane); __syncthreads();
    softmax_rows(Sb, wid, lane); __syncthreads();

    load_feat(fb, low2, rb, tid); __syncthreads();
    apply_gemm<false>(fb, Sb, t, wid, lane);
    emit_add(outL, t, rb, wid, lane); __syncthreads();

    load_feat(fb, low1, rb, tid); __syncthreads();
    apply_gemm<true>(fb, Sb, t, wid, lane);
    emit_add(outR, t, rb, wid, lane); __syncthreads();

    load_feat(fb, l2r1s, rb, tid); __syncthreads();
    apply_gemm<false>(fb, Sb, t, wid, lane);
    emit_add(outL, t, rb, wid, lane); __syncthreads();

    load_feat(fb, r2l1s, rb, tid); __syncthreads();
    apply_gemm<true>(fb, Sb, t, wid, lane);
    emit_add(outR, t, rb, wid, lane);
}

// =================================================================================
extern "C" void kernel_launch(void* const* d_in, const int* in_sizes, int n_in,
                              void* d_out, int out_size)
{
    const float* low1   = (const float*)d_in[0];
    const float* low2   = (const float*)d_in[1];
    const float* fe1_w1 = (const float*)d_in[2];
    const float* fe1_b1 = (const float*)d_in[3];
    const float* fe1_w2 = (const float*)d_in[4];
    const float* fe1_b2 = (const float*)d_in[5];
    const float* fe2_w1 = (const float*)d_in[6];
    const float* fe2_b1 = (const float*)d_in[7];
    const float* fe2_w2 = (const float*)d_in[8];
    const float* fe2_b2 = (const float*)d_in[9];
    const float* conv_w = (const float*)d_in[10];
    const float* conv_b = (const float*)d_in[11];
    float* out = (float*)d_out;

    float *t_, *a_, *q1, *k1, *q2, *k2, *r2l1, *l2r1;
    cudaGetSymbolAddress((void**)&t_,   g_t);
    cudaGetSymbolAddress((void**)&a_,   g_a);
    cudaGetSymbolAddress((void**)&q1,   g_Q1);
    cudaGetSymbolAddress((void**)&k1,   g_K1);
    cudaGetSymbolAddress((void**)&q2,   g_Q2);
    cudaGetSymbolAddress((void**)&k2,   g_K2);
    cudaGetSymbolAddress((void**)&r2l1, g_r2l1);
    cudaGetSymbolAddress((void**)&l2r1, g_l2r1);

    static int conv_attr_set = 0;
    if (!conv_attr_set) {
        cudaFuncSetAttribute(conv3x3_mma,
                             cudaFuncAttributeMaxDynamicSharedMemorySize,
                             CONV_SMEM_BYTES);
        cudaFuncSetAttribute(attn_kernel,
                             cudaFuncAttributeMaxDynamicSharedMemorySize,
                             (192 * SP + 64 * 192) * (int)sizeof(float));
        conv_attr_set = 1;
    }

    const dim3 cgrid(WW / 16, HH / 16, BB);

    struct Combo { const float* src; const float *w1, *b1, *w2, *b2; float* dst; };
    Combo combos[4] = {
        { low1, fe1_w1, fe1_b1, fe1_w2, fe1_b2, q1 },
        { low2, fe1_w1, fe1_b1, fe1_w2, fe1_b2, k1 },
        { low1, fe2_w1, fe2_b1, fe2_w2, fe2_b2, q2 },
        { low2, fe2_w1, fe2_b1, fe2_w2, fe2_b2, k2 },
    };
    for (int i = 0; i < 4; i++) {
        conv3x3_mma<<<cgrid, 256, CONV_SMEM_BYTES>>>(
            combos[i].src, combos[i].w1, combos[i].b1, nullptr, t_, 1);
        conv3x3_mma<<<cgrid, 256, CONV_SMEM_BYTES>>>(
            t_, combos[i].w2, combos[i].b2, combos[i].src, a_, 2);
        conv3x3_mma<<<cgrid, 256, CONV_SMEM_BYTES>>>(
            a_, conv_w, conv_b, nullptr, combos[i].dst, 0);
    }

    const int smem_bytes = (192 * SP + 64 * 192) * (int)sizeof(float); // 197376
    attn_kernel<<<dim3(HH, BB), 256, smem_bytes>>>(
        low1, low2, q1, k1, q2, k2, r2l1, l2r1, out, out + NT);
}

// round 3
// speedup vs baseline: 3.1882x; 1.8692x over previous
#include <cuda_runtime.h>
#include <cuda_bf16.h>

typedef unsigned int u32;
typedef unsigned long long u64;

// Problem constants
#define BB 4
#define CC 64
#define HH 192
#define WW 192
#define CS (HH*WW)            // channel stride = 36864
#define NT (BB*CC*HH*WW)      // elems per [B,C,H,W] fp32 tensor
#define PT (BB*32*CS)         // elems per packed tensor (uint2 per channel-pair)
#define SP 193                // padded row stride for score matrix in SMEM

// ---------------- static scratch (no runtime allocation allowed) ----------------
__device__ uint2 g_low1p[PT];
__device__ uint2 g_low2p[PT];
__device__ uint2 g_tp[4 * PT];      // packed conv1 outputs, per combo
__device__ uint2 g_ap[4 * PT];      // packed conv2 outputs, per combo
__device__ uint4 g_wp[5][9216];     // prepacked weights: fe1w1,fe1w2,fe2w1,fe2w2,convw
__device__ float g_qk[4 * NT];      // Q1,K1,Q2,K2
__device__ float g_r2l1[NT];
__device__ float g_l2r1[NT];

// ---------------- helpers ----------------
__device__ __forceinline__ void split_pack(float ev, float ov, u32 &hi, u32 &lo)
{
    __nv_bfloat16 eh = __float2bfloat16(ev);
    __nv_bfloat16 oh = __float2bfloat16(ov);
    __nv_bfloat16 el = __float2bfloat16(ev - __bfloat162float(eh));
    __nv_bfloat16 ol = __float2bfloat16(ov - __bfloat162float(oh));
    hi = (u32)__bfloat16_as_ushort(eh) | ((u32)__bfloat16_as_ushort(oh) << 16);
    lo = (u32)__bfloat16_as_ushort(el) | ((u32)__bfloat16_as_ushort(ol) << 16);
}

__device__ __forceinline__ void mma16816(float c[4],
                                         u32 a0, u32 a1, u32 a2, u32 a3,
                                         u32 b0, u32 b1)
{
    asm volatile(
        "mma.sync.aligned.m16n8k16.row.col.f32.bf16.bf16.f32 "
        "{%0,%1,%2,%3}, {%4,%5,%6,%7}, {%8,%9}, {%0,%1,%2,%3};"
        : "+f"(c[0]), "+f"(c[1]), "+f"(c[2]), "+f"(c[3])
        : "r"(a0), "r"(a1), "r"(a2), "r"(a3), "r"(b0), "r"(b1));
}

__device__ __forceinline__ u64 pk2(float lo, float hi)
{
    u64 r;
    asm("mov.b64 %0, {%1,%2};" : "=l"(r) : "f"(lo), "f"(hi));
    return r;
}
__device__ __forceinline__ void upk2(u64 v, float &lo, float &hi)
{
    asm("mov.b64 {%0,%1}, %2;" : "=f"(lo), "=f"(hi) : "l"(v));
}
__device__ __forceinline__ void ffma2(u64 &d, u64 a, u64 b)
{
    asm("fma.rn.f32x2 %0, %1, %2, %0;" : "+l"(d) : "l"(a), "l"(b));
}

// =================================================================================
// Prep kernels (run each launch; tiny)
// =================================================================================
// weights: w[o*576 + c*9 + tap]  ->  wp[((tap*4+chunk)*64+o)*4+t] = {hi(c2=chunk*8+t),
//          hi(c2=chunk*8+t+4), lo(..t), lo(..t+4)}  where pair c2 = channels 2c2,2c2+1
__global__ void pack_weights(const float* __restrict__ w, uint4* __restrict__ wp)
{
    int idx = blockIdx.x * 256 + threadIdx.x;
    if (idx >= 9216) return;
    int tap = idx >> 10, rem = idx & 1023;
    int chunk = rem >> 8, rem2 = rem & 255;
    int o = rem2 >> 2, t = rem2 & 3;
    int c2a = chunk * 8 + t, c2b = c2a + 4;
    u32 h0, l0, h1, l1;
    split_pack(__ldg(&w[o * 576 + (2 * c2a) * 9 + tap]),
               __ldg(&w[o * 576 + (2 * c2a + 1) * 9 + tap]), h0, l0);
    split_pack(__ldg(&w[o * 576 + (2 * c2b) * 9 + tap]),
               __ldg(&w[o * 576 + (2 * c2b + 1) * 9 + tap]), h1, l1);
    wp[idx] = make_uint4(h0, h1, l0, l1);
}

// features: fp32 [B,64,H,W] -> packed uint2{hi,lo} [B,32,H,W] (channel pairs)
__global__ void pack_features(const float* __restrict__ x, uint2* __restrict__ xp)
{
    int i = blockIdx.x * 256 + threadIdx.x;
    if (i >= PT) return;
    int pos = i % CS;
    int bc2 = i / CS;           // b*32 + c2
    int b = bc2 >> 5, c2 = bc2 & 31;
    const float* p = x + ((b * 64 + 2 * c2) * CS) + pos;
    u32 h, l;
    split_pack(p[0], p[CS], h, l);
    xp[i] = make_uint2(h, l);
}

// =================================================================================
// Tensor-core conv 3x3 (stride1 pad1 C64->C64), bf16x3 split, prepacked I/O.
// grid (12,12,16): blockIdx.z -> combo = z>>2 (0..3), b = z&3.
// combo&1 selects input A/B + skip A/B ; combo>>1 selects weight/bias A/B.
// mode 1: relu -> packed out ; mode 2: +skip -> packed out ; mode 0: fp32 out.
// One __syncthreads total. B-fragments via LDG.128 from prepacked weights.
// =================================================================================
#define CONV_SMEM_BYTES (23040*4)

__global__ void __launch_bounds__(256, 2) conv3x3_tc(
    const uint2* __restrict__ xpA, const uint2* __restrict__ xpB, int xstride,
    const uint4* __restrict__ wpA, const uint4* __restrict__ wpB,
    const float* __restrict__ bsA, const float* __restrict__ bsB,
    const float* __restrict__ skA, const float* __restrict__ skB,
    float* __restrict__ yf, uint2* __restrict__ yp, int mode)
{
    extern __shared__ u32 smc[];
    u32* Hhi = smc;
    u32* Hlo = smc + 11520;

    const int bz = blockIdx.z;
    const int combo = bz >> 2, b = bz & 3;
    const uint2* xp = ((combo & 1) ? xpB : xpA) + (size_t)combo * xstride;
    const uint4* wp = (combo >> 1) ? wpB : wpA;
    const float* bias = (combo >> 1) ? bsB : bsA;
    const float* skip = (combo & 1) ? skB : skA;

    const int ty = blockIdx.y, tx = blockIdx.x;
    const int tid = threadIdx.x, wid = tid >> 5, lane = tid & 31;
    const int g = lane >> 2, t = lane & 3;

    // ---- stage packed halo (18x18, zero-padded at image border) ----
    const int y0 = ty * 16 - 1, x0 = tx * 16 - 1;
    for (int i = tid; i < 32 * 18 * 18; i += 256) {
        int c2 = i / 324, r = i % 324;
        int yy = r / 18, xx = r % 18;
        int gy = y0 + yy, gx = x0 + xx;
        uint2 v = make_uint2(0u, 0u);
        if (gy >= 0 && gy < HH && gx >= 0 && gx < WW)
            v = __ldg(&xp[(b * 32 + c2) * CS + gy * WW + gx]);
        Hhi[c2 * 360 + yy * 20 + xx] = v.x;
        Hlo[c2 * 360 + yy * 20 + xx] = v.y;
    }
    __syncthreads();

    float acc[2][8][4];
#pragma unroll
    for (int mi = 0; mi < 2; mi++)
#pragma unroll
        for (int n8 = 0; n8 < 8; n8++)
#pragma unroll
            for (int q = 0; q < 4; q++) acc[mi][n8][q] = 0.f;

    const int row0 = 2 * wid;

    for (int tap = 0; tap < 9; tap++) {
        const int dy = tap / 3, dx = tap % 3;
#pragma unroll
        for (int ch = 0; ch < 4; ch++) {
            const int c2b = ch * 8;
            u32 ah[2][4], al[2][4];
#pragma unroll
            for (int mi = 0; mi < 2; mi++) {
                const int base = (row0 + mi + dy) * 20 + dx;
                const int rA = (c2b + t) * 360 + base;
                const int rB = (c2b + t + 4) * 360 + base;
                ah[mi][0] = Hhi[rA + g];
                ah[mi][1] = Hhi[rA + g + 8];
                ah[mi][2] = Hhi[rB + g];
                ah[mi][3] = Hhi[rB + g + 8];
                al[mi][0] = Hlo[rA + g];
                al[mi][1] = Hlo[rA + g + 8];
                al[mi][2] = Hlo[rB + g];
                al[mi][3] = Hlo[rB + g + 8];
            }
            const uint4* wrow = wp + ((tap * 4 + ch) * 64) * 4 + t;
#pragma unroll
            for (int n8 = 0; n8 < 8; n8++) {
                uint4 Bv = __ldg(&wrow[(n8 * 8 + g) * 4]);
#pragma unroll
                for (int mi = 0; mi < 2; mi++) {
                    mma16816(acc[mi][n8], ah[mi][0], ah[mi][1], ah[mi][2], ah[mi][3], Bv.x, Bv.y);
                    mma16816(acc[mi][n8], ah[mi][0], ah[mi][1], ah[mi][2], ah[mi][3], Bv.z, Bv.w);
                    mma16816(acc[mi][n8], al[mi][0], al[mi][1], al[mi][2], al[mi][3], Bv.x, Bv.y);
                }
            }
        }
    }

    // ---- epilogue ----
    const int gyb = ty * 16 + row0, gxb = tx * 16;
    if (mode == 0) {
        float* yfc = yf + (size_t)combo * NT;
#pragma unroll
        for (int n8 = 0; n8 < 8; n8++) {
#pragma unroll
            for (int mi = 0; mi < 2; mi++) {
                const int gy = gyb + mi;
#pragma unroll
                for (int q = 0; q < 4; q++) {
                    const int och = n8 * 8 + 2 * t + (q & 1);
                    const int px  = gxb + g + ((q >= 2) ? 8 : 0);
                    yfc[((b * 64 + och) * HH + gy) * WW + px] =
                        acc[mi][n8][q] + __ldg(&bias[och]);
                }
            }
        }
    } else {
        uint2* ypc = yp + (size_t)combo * PT;
#pragma unroll
        for (int n8 = 0; n8 < 8; n8++) {
            const int och0 = n8 * 8 + 2 * t;
            const float b0 = __ldg(&bias[och0]);
            const float b1 = __ldg(&bias[och0 + 1]);
            const int c2o = n8 * 4 + t;
#pragma unroll
            for (int mi = 0; mi < 2; mi++) {
                const int gy = gyb + mi;
#pragma unroll
                for (int half = 0; half < 2; half++) {
                    const int px = gxb + g + half * 8;
                    float v0 = acc[mi][n8][half * 2 + 0] + b0;
                    float v1 = acc[mi][n8][half * 2 + 1] + b1;
                    if (mode == 1) {
                        v0 = fmaxf(v0, 0.f);
                        v1 = fmaxf(v1, 0.f);
                    } else {
                        const int off = ((b * 64 + och0) * HH + gy) * WW + px;
                        v0 += __ldg(&skip[off]);
                        v1 += __ldg(&skip[off + CS]);
                    }
                    u32 h, l;
                    split_pack(v0, v1, h, l);
                    ypc[(b * 32 + c2o) * CS + gy * WW + px] = make_uint2(h, l);
                }
            }
        }
    }
}

// =================================================================================
// Fused attention: one CTA per (b, h). 256 threads = 8 warps.
// SMEM: Sb[192][193] fp32 scores + fb channel-pair-interleaved features (48 KB).
// Inner loops use packed fp32x2 FMA (fma.rn.f32x2) -> half the FMA instructions.
// =================================================================================

// fb layout: u64 fbu[c2*192 + v] = pack(feat[2c2][v], feat[2c2+1][v])
__device__ __forceinline__ void load_feat(float* fbf, const float* __restrict__ gsrc,
                                          int rb, int tid)
{
#pragma unroll
    for (int k = 0; k < 6; k++) {
        int i4 = tid + k * 256;          // 0..1535 over (c2, v4)
        int c2 = i4 / 48, v4 = i4 % 48;
        float4 a4 = *(const float4*)(gsrc + rb + (2 * c2) * CS + v4 * 4);
        float4 b4 = *(const float4*)(gsrc + rb + (2 * c2 + 1) * CS + v4 * 4);
        float4* dst = (float4*)(fbf + (c2 * 192 + v4 * 4) * 2);
        dst[0] = make_float4(a4.x, b4.x, a4.y, b4.y);
        dst[1] = make_float4(a4.z, b4.z, a4.w, b4.w);
    }
}

// S[w][v] = sum_c Q[c][w] * K[c][v]
__device__ __forceinline__ void compute_S(const float* __restrict__ Q, int rb,
                                          const u64* fbu, float* Sb,
                                          int wid, int lane)
{
    const int w0 = wid * 24;
    for (int gg = 0; gg < 6; gg++) {
        const int wr = w0 + gg * 4;
        u64 accp[4][6];
#pragma unroll
        for (int r = 0; r < 4; r++)
#pragma unroll
            for (int j = 0; j < 6; j++) accp[r][j] = 0ull;

        for (int c2 = 0; c2 < 32; c2++) {
            float4 q0 = __ldg((const float4*)(Q + rb + (2 * c2) * CS + wr));
            float4 q1 = __ldg((const float4*)(Q + rb + (2 * c2 + 1) * CS + wr));
            u64 aq0 = pk2(q0.x, q1.x), aq1 = pk2(q0.y, q1.y);
            u64 aq2 = pk2(q0.z, q1.z), aq3 = pk2(q0.w, q1.w);
#pragma unroll
            for (int j = 0; j < 6; j++) {
                u64 kv = fbu[c2 * 192 + lane + 32 * j];
                ffma2(accp[0][j], aq0, kv);
                ffma2(accp[1][j], aq1, kv);
                ffma2(accp[2][j], aq2, kv);
                ffma2(accp[3][j], aq3, kv);
            }
        }
#pragma unroll
        for (int r = 0; r < 4; r++)
#pragma unroll
            for (int j = 0; j < 6; j++) {
                float lo, hi;
                upk2(accp[r][j], lo, hi);
                Sb[(wr + r) * SP + lane + 32 * j] = lo + hi;
            }
    }
}

__device__ __forceinline__ void softmax_rows(float* Sb, int wid, int lane)
{
    for (int r = wid * 24; r < wid * 24 + 24; r++) {
        float v[6];
        float m = -1e30f;
#pragma unroll
        for (int j = 0; j < 6; j++) {
            v[j] = Sb[r * SP + lane + 32 * j];
            m = fmaxf(m, v[j]);
        }
#pragma unroll
        for (int o = 16; o > 0; o >>= 1)
            m = fmaxf(m, __shfl_xor_sync(0xffffffffu, m, o));
        float s = 0.f;
#pragma unroll
        for (int j = 0; j < 6; j++) { v[j] = __expf(v[j] - m); s += v[j]; }
#pragma unroll
        for (int o = 16; o > 0; o >>= 1)
            s += __shfl_xor_sync(0xffffffffu, s, o);
        float inv = 1.0f / s;
#pragma unroll
        for (int j = 0; j < 6; j++)
            Sb[r * SP + lane + 32 * j] = v[j] * inv;
    }
}

// TRANSP=false : out[c][w] = sum_v f[c][v] * S[w][v]
// TRANSP=true  : out[c][w] = sum_v f[c][v] * S[v][w]
template <bool TRANSP>
__device__ __forceinline__ void apply_gemm(const u64* fbu, const float* Sb,
                                           float t[48], int wid, int lane)
{
    u64 acc2[4][6];
#pragma unroll
    for (int ci2 = 0; ci2 < 4; ci2++)
#pragma unroll
        for (int j = 0; j < 6; j++) acc2[ci2][j] = 0ull;

    const int fbase = wid * 4 * 192;
    for (int v = 0; v < 192; v += 4) {
        u64 fp[4][4];
#pragma unroll
        for (int ci2 = 0; ci2 < 4; ci2++) {
            ulonglong2 u0 = *(const ulonglong2*)(fbu + fbase + ci2 * 192 + v);
            ulonglong2 u1 = *(const ulonglong2*)(fbu + fbase + ci2 * 192 + v + 2);
            fp[ci2][0] = u0.x; fp[ci2][1] = u0.y;
            fp[ci2][2] = u1.x; fp[ci2][3] = u1.y;
        }
#pragma unroll
        for (int dv = 0; dv < 4; dv++) {
#pragma unroll
            for (int j = 0; j < 6; j++) {
                float s = TRANSP ? Sb[(v + dv) * SP + lane + 32 * j]
                                 : Sb[(lane + 32 * j) * SP + (v + dv)];
                u64 s2 = pk2(s, s);
                ffma2(acc2[0][j], fp[0][dv], s2);
                ffma2(acc2[1][j], fp[1][dv], s2);
                ffma2(acc2[2][j], fp[2][dv], s2);
                ffma2(acc2[3][j], fp[3][dv], s2);
            }
        }
    }
#pragma unroll
    for (int ci2 = 0; ci2 < 4; ci2++)
#pragma unroll
        for (int j = 0; j < 6; j++) {
            float lo, hi;
            upk2(acc2[ci2][j], lo, hi);
            t[(2 * ci2) * 6 + j] = lo;
            t[(2 * ci2 + 1) * 6 + j] = hi;
        }
}

__device__ __forceinline__ void emit_init(float* dst, float* scratch,
                                          const float* base, const float t[48],
                                          int rb, int wid, int lane)
{
    const int c0 = wid * 8;
#pragma unroll
    for (int ci = 0; ci < 8; ci++)
#pragma unroll
        for (int j = 0; j < 6; j++) {
            int off = rb + (c0 + ci) * CS + lane + 32 * j;
            float v = t[ci * 6 + j];
            scratch[off] = v;
            dst[off] = base[off] + v;
        }
}

__device__ __forceinline__ void emit_add(float* dst, const float t[48],
                                         int rb, int wid, int lane)
{
    const int c0 = wid * 8;
#pragma unroll
    for (int ci = 0; ci < 8; ci++)
#pragma unroll
        for (int j = 0; j < 6; j++) {
            int off = rb + (c0 + ci) * CS + lane + 32 * j;
            dst[off] += t[ci * 6 + j];
        }
}

__global__ void __launch_bounds__(256, 1) attn_kernel(
    const float* __restrict__ low1, const float* __restrict__ low2,
    const float* __restrict__ Q1, const float* __restrict__ K1,
    const float* __restrict__ Q2, const float* __restrict__ K2,
    float* __restrict__ r2l1s, float* __restrict__ l2r1s,
    float* __restrict__ outL, float* __restrict__ outR)
{
    extern __shared__ float smf[];
    float* Sb  = smf;
    float* fbf = smf + 192 * SP;          // 16B-aligned (192*193*4 % 16 == 0)
    const u64* fbu = (const u64*)fbf;

    const int h = blockIdx.x, b = blockIdx.y;
    const int tid = threadIdx.x, wid = tid >> 5, lane = tid & 31;
    const int rb = b * 64 * CS + h * WW;
    float t[48];

    // ---- stage 1: S1 = softmax(Q1^T K1) ----
    load_feat(fbf, K1, rb, tid); __syncthreads();
    compute_S(Q1, rb, fbu, Sb, wid, lane); __syncthreads();
    softmax_rows(Sb, wid, lane); __syncthreads();

    load_feat(fbf, low2, rb, tid); __syncthreads();
    apply_gemm<false>(fbu, Sb, t, wid, lane);
    emit_init(outL, r2l1s, low1, t, rb, wid, lane);
    __syncthreads();

    load_feat(fbf, low1, rb, tid); __syncthreads();
    apply_gemm<true>(fbu, Sb, t, wid, lane);
    emit_init(outR, l2r1s, low2, t, rb, wid, lane);
    __syncthreads();

    // ---- stage 2: S2 = softmax(Q2^T K2) ----
    load_feat(fbf, K2, rb, tid); __syncthreads();
    compute_S(Q2, rb, fbu, Sb, wid, lane); __syncthreads();
    softmax_rows(Sb, wid, lane); __syncthreads();

    load_feat(fbf, low2, rb, tid); __syncthreads();
    apply_gemm<false>(fbu, Sb, t, wid, lane);
    emit_add(outL, t, rb, wid, lane); __syncthreads();

    load_feat(fbf, low1, rb, tid); __syncthreads();
    apply_gemm<true>(fbu, Sb, t, wid, lane);
    emit_add(outR, t, rb, wid, lane); __syncthreads();

    load_feat(fbf, l2r1s, rb, tid); __syncthreads();
    apply_gemm<false>(fbu, Sb, t, wid, lane);
    emit_add(outL, t, rb, wid, lane); __syncthreads();

    load_feat(fbf, r2l1s, rb, tid); __syncthreads();
    apply_gemm<true>(fbu, Sb, t, wid, lane);
    emit_add(outR, t, rb, wid, lane);
}

// =================================================================================
extern "C" void kernel_launch(void* const* d_in, const int* in_sizes, int n_in,
                              void* d_out, int out_size)
{
    const float* low1   = (const float*)d_in[0];
    const float* low2   = (const float*)d_in[1];
    const float* fe1_w1 = (const float*)d_in[2];
    const float* fe1_b1 = (const float*)d_in[3];
    const float* fe1_w2 = (const float*)d_in[4];
    const float* fe1_b2 = (const float*)d_in[5];
    const float* fe2_w1 = (const float*)d_in[6];
    const float* fe2_b1 = (const float*)d_in[7];
    const float* fe2_w2 = (const float*)d_in[8];
    const float* fe2_b2 = (const float*)d_in[9];
    const float* conv_w = (const float*)d_in[10];
    const float* conv_b = (const float*)d_in[11];
    float* out = (float*)d_out;

    uint2 *low1p, *low2p, *tp, *ap;
    uint4 *wp;
    float *qk, *r2l1, *l2r1;
    cudaGetSymbolAddress((void**)&low1p, g_low1p);
    cudaGetSymbolAddress((void**)&low2p, g_low2p);
    cudaGetSymbolAddress((void**)&tp,    g_tp);
    cudaGetSymbolAddress((void**)&ap,    g_ap);
    cudaGetSymbolAddress((void**)&wp,    g_wp);
    cudaGetSymbolAddress((void**)&qk,    g_qk);
    cudaGetSymbolAddress((void**)&r2l1,  g_r2l1);
    cudaGetSymbolAddress((void**)&l2r1,  g_l2r1);

    uint4* wp_fe1w1 = wp + 0 * 9216;
    uint4* wp_fe1w2 = wp + 1 * 9216;
    uint4* wp_fe2w1 = wp + 2 * 9216;
    uint4* wp_fe2w2 = wp + 3 * 9216;
    uint4* wp_convw = wp + 4 * 9216;

    cudaFuncSetAttribute(conv3x3_tc,
                         cudaFuncAttributeMaxDynamicSharedMemorySize,
                         CONV_SMEM_BYTES);
    const int attn_smem = (192 * SP + 2 * 32 * 192) * (int)sizeof(float); // 197376
    cudaFuncSetAttribute(attn_kernel,
                         cudaFuncAttributeMaxDynamicSharedMemorySize, attn_smem);

    // ---- prep: pack weights + inputs ----
    pack_weights<<<36, 256>>>(fe1_w1, wp_fe1w1);
    pack_weights<<<36, 256>>>(fe1_w2, wp_fe1w2);
    pack_weights<<<36, 256>>>(fe2_w1, wp_fe2w1);
    pack_weights<<<36, 256>>>(fe2_w2, wp_fe2w2);
    pack_weights<<<36, 256>>>(conv_w, wp_convw);
    pack_features<<<(PT + 255) / 256, 256>>>(low1, low1p);
    pack_features<<<(PT + 255) / 256, 256>>>(low2, low2p);

    const dim3 cgrid(WW / 16, HH / 16, 4 * BB);

    // stage 1: t[combo] = relu(conv(low{1,2}, fe{1,2}_w1) + b1)   (packed out)
    conv3x3_tc<<<cgrid, 256, CONV_SMEM_BYTES>>>(
        low1p, low2p, 0, wp_fe1w1, wp_fe2w1, fe1_b1, fe2_b1,
        nullptr, nullptr, nullptr, tp, 1);
    // stage 2: a[combo] = low + conv(t, fe_w2) + b2               (packed out)
    conv3x3_tc<<<cgrid, 256, CONV_SMEM_BYTES>>>(
        tp, tp, PT, wp_fe1w2, wp_fe2w2, fe1_b2, fe2_b2,
        low1, low2, nullptr, ap, 2);
    // stage 3: qk[combo] = conv(a, conv_w) + conv_b               (fp32 out)
    conv3x3_tc<<<cgrid, 256, CONV_SMEM_BYTES>>>(
        ap, ap, PT, wp_convw, wp_convw, conv_b, conv_b,
        nullptr, nullptr, qk, nullptr, 0);

    attn_kernel<<<dim3(HH, BB), 256, attn_smem>>>(
        low1, low2, qk, qk + NT, qk + 2 * NT, qk + 3 * NT,
        r2l1, l2r1, out, out + NT);
}